// round 3
// baseline (speedup 1.0000x reference)
#include <cuda_runtime.h>

#define B_ 8
#define C_ 64
#define H_ 256
#define W_ 256
#define HW_ (H_ * W_)
#define FULLMASK 0xffffffffu

// 4 px/thread (aligned float4). Warp = 32 lanes = 128 contiguous px of one row.
// Neighbor taps (w-1, w+4) come from lane shuffles; only the warp-edge lanes
// issue a single predicated scalar load per row. h is warp-uniform.
__global__ __launch_bounds__(128, 8)
void conv_attn_shfl(const float* __restrict__ q,
                    const float* __restrict__ k,
                    const float* __restrict__ v,
                    float* __restrict__ out)
{
    const int lane = threadIdx.x & 31;
    const int w0   = threadIdx.x * 4;             // 0..252
    const int h    = blockIdx.y * 2 + threadIdx.y;
    const int b    = blockIdx.z;

    const size_t cb = (size_t)b * C_ * HW_;
    const int rowoff = h * W_ + w0;

    float s[4][9];
#pragma unroll
    for (int j = 0; j < 4; j++)
#pragma unroll
        for (int i = 0; i < 9; i++) s[j][i] = 0.0f;

    // ---------------- Pass 1: scores ----------------
#pragma unroll 2
    for (int c = 0; c < C_; c++) {
        const float* qc = q + cb + (size_t)c * HW_;
        const float* kc = k + cb + (size_t)c * HW_;

        const float4 qv = *reinterpret_cast<const float4*>(qc + rowoff);
        const float qa[4] = {qv.x, qv.y, qv.z, qv.w};

#pragma unroll
        for (int dy = 0; dy < 3; dy++) {
            const int hh = h + dy - 1;
            if (hh < 0 || hh >= H_) continue;     // warp-uniform
            const float* row = kc + hh * W_ + w0;

            const float4 m = *reinterpret_cast<const float4*>(row);
            float left  = __shfl_up_sync(FULLMASK, m.w, 1);
            float right = __shfl_down_sync(FULLMASK, m.x, 1);
            if (lane == 0)  left  = (w0 > 0)      ? row[-1] : 0.0f;
            if (lane == 31) right = (w0 + 4 < W_) ? row[4]  : 0.0f;

            const float a[6] = {left, m.x, m.y, m.z, m.w, right};
#pragma unroll
            for (int j = 0; j < 4; j++)
#pragma unroll
                for (int dx = 0; dx < 3; dx++)
                    s[j][dy * 3 + dx] = fmaf(qa[j], a[j + dx], s[j][dy * 3 + dx]);
        }
    }

    // ---------------- Softmax over 9 taps (OOB taps carry score 0) ----------------
#pragma unroll
    for (int j = 0; j < 4; j++) {
        float mx = s[j][0];
#pragma unroll
        for (int i = 1; i < 9; i++) mx = fmaxf(mx, s[j][i]);
        float sum = 0.0f;
#pragma unroll
        for (int i = 0; i < 9; i++) { s[j][i] = __expf(s[j][i] - mx); sum += s[j][i]; }
        const float inv = 1.0f / sum;
#pragma unroll
        for (int i = 0; i < 9; i++) s[j][i] *= inv;
    }

    // ---------------- Pass 2: weighted v sum ----------------
#pragma unroll 2
    for (int c = 0; c < C_; c++) {
        const float* vc = v + cb + (size_t)c * HW_;

        float acc[4] = {0.0f, 0.0f, 0.0f, 0.0f};

#pragma unroll
        for (int dy = 0; dy < 3; dy++) {
            const int hh = h + dy - 1;
            if (hh < 0 || hh >= H_) continue;
            const float* row = vc + hh * W_ + w0;

            const float4 m = *reinterpret_cast<const float4*>(row);
            float left  = __shfl_up_sync(FULLMASK, m.w, 1);
            float right = __shfl_down_sync(FULLMASK, m.x, 1);
            if (lane == 0)  left  = (w0 > 0)      ? row[-1] : 0.0f;
            if (lane == 31) right = (w0 + 4 < W_) ? row[4]  : 0.0f;

            const float a[6] = {left, m.x, m.y, m.z, m.w, right};
#pragma unroll
            for (int j = 0; j < 4; j++)
#pragma unroll
                for (int dx = 0; dx < 3; dx++)
                    acc[j] = fmaf(s[j][dy * 3 + dx], a[j + dx], acc[j]);
        }

        float4 o;
        o.x = acc[0]; o.y = acc[1]; o.z = acc[2]; o.w = acc[3];
        *reinterpret_cast<float4*>(out + cb + (size_t)c * HW_ + rowoff) = o;
    }
}

extern "C" void kernel_launch(void* const* d_in, const int* in_sizes, int n_in,
                              void* d_out, int out_size)
{
    const float* q = (const float*)d_in[0];
    const float* k = (const float*)d_in[1];
    const float* v = (const float*)d_in[2];
    float* out = (float*)d_out;

    dim3 block(64, 2);          // 128 threads: 2 warps per row x 2 rows
    dim3 grid(1, H_ / 2, B_);   // 1024 blocks
    conv_attn_shfl<<<grid, block>>>(q, k, v, out);
}

// round 4
// speedup vs baseline: 1.5679x; 1.5679x over previous
#include <cuda_runtime.h>
#include <cstdint>

#define B_ 8
#define C_ 64
#define H_ 256
#define W_ 256
#define HW_ (H_ * W_)
#define TH 4                  // output rows per block
#define ROWS (TH + 2)         // staged input rows (with halo)
#define NS 4                  // pipeline depth (ring buffers)
#define RSTRIDE 264           // floats per smem row (4 guard | 256 data | 1 guard | pad)
// smem row layout: idx 3 = zero guard (w=-1), idx 4..259 = data w=0..255, idx 260 = zero guard (w=256)

__device__ __forceinline__ void cp16(uint32_t dst, const float* src) {
    asm volatile("cp.async.cg.shared.global [%0], [%1], 16;" :: "r"(dst), "l"(src));
}
__device__ __forceinline__ void cp_commit() {
    asm volatile("cp.async.commit_group;");
}
__device__ __forceinline__ void cp_wait3() {
    asm volatile("cp.async.wait_group 3;");
}

__global__ __launch_bounds__(256, 4)
void conv_attn_pipe(const float* __restrict__ q, const float* __restrict__ k,
                    const float* __restrict__ v, float* __restrict__ out)
{
    __shared__ __align__(16) float ring[NS][ROWS][RSTRIDE];

    const int tid = threadIdx.x;
    const int x   = tid & 63;          // w-group: 64 groups of 4 px
    const int y   = tid >> 6;          // output row within tile: 0..3
    const int w0  = x * 4;
    const int h0  = blockIdx.x * TH;
    const int b   = blockIdx.y;

    const size_t cb = (size_t)b * C_ * HW_;
    const float* qb = q + cb;
    const float* kb = k + cb;
    const float* vb = v + cb;
    float*       ob = out + cb;
    const int rowoff = (h0 + y) * W_ + w0;

    // zero the guard cells once (never overwritten by staging)
    for (int i = tid; i < NS * ROWS; i += 256) {
        ring[i / ROWS][i % ROWS][3]   = 0.0f;
        ring[i / ROWS][i % ROWS][260] = 0.0f;
    }

    const uint32_t ring_s = (uint32_t)__cvta_generic_to_shared(&ring[0][0][0]);

    // stage channel c of tensor base `srcb` into ring[c % NS]
    auto stage = [&](const float* srcb, int c) {
        const int      bi   = c & (NS - 1);
        const uint32_t bufb = ring_s + (uint32_t)bi * (ROWS * RSTRIDE * 4);
        const float*   chan = srcb + (size_t)c * HW_;
        #pragma unroll
        for (int slot = tid; slot < ROWS * 64; slot += 256) {
            const int r   = slot >> 6;
            const int col = (slot & 63) * 4;
            const int hh  = h0 - 1 + r;
            if (hh >= 0 && hh < H_) {
                cp16(bufb + (uint32_t)(r * RSTRIDE + 4 + col) * 4, chan + hh * W_ + col);
            } else {
                float4 z = make_float4(0.f, 0.f, 0.f, 0.f);
                *reinterpret_cast<float4*>(&ring[bi][r][4 + col]) = z;
            }
        }
    };

    float s[4][9];
#pragma unroll
    for (int j = 0; j < 4; j++)
#pragma unroll
        for (int i = 0; i < 9; i++) s[j][i] = 0.0f;

    // ================= Pass 1: scores =================
    for (int c = 0; c < 3; c++) { stage(kb, c); cp_commit(); }
    float4 qcur = *reinterpret_cast<const float4*>(qb + rowoff);   // q(0)

#pragma unroll 1
    for (int c = 0; c < C_; c++) {
        if (c + 3 < C_) stage(kb, c + 3);
        cp_commit();
        cp_wait3();
        __syncthreads();

        // prefetch q for next channel
        float4 qnext;
        if (c + 1 < C_)
            qnext = *reinterpret_cast<const float4*>(qb + (size_t)(c + 1) * HW_ + rowoff);

        const float qa[4] = {qcur.x, qcur.y, qcur.z, qcur.w};
        const int bi = c & (NS - 1);
#pragma unroll
        for (int dy = 0; dy < 3; dy++) {
            const float* rp = &ring[bi][y + dy][4 + w0];
            const float4 m = *reinterpret_cast<const float4*>(rp);
            const float a[6] = {rp[-1], m.x, m.y, m.z, m.w, rp[4]};
#pragma unroll
            for (int j = 0; j < 4; j++)
#pragma unroll
                for (int dx = 0; dx < 3; dx++)
                    s[j][dy * 3 + dx] = fmaf(qa[j], a[j + dx], s[j][dy * 3 + dx]);
        }
        qcur = qnext;
        __syncthreads();
    }

    // ================= Softmax over 9 taps =================
#pragma unroll
    for (int j = 0; j < 4; j++) {
        float mx = s[j][0];
#pragma unroll
        for (int i = 1; i < 9; i++) mx = fmaxf(mx, s[j][i]);
        float sum = 0.0f;
#pragma unroll
        for (int i = 0; i < 9; i++) { s[j][i] = __expf(s[j][i] - mx); sum += s[j][i]; }
        const float inv = 1.0f / sum;
#pragma unroll
        for (int i = 0; i < 9; i++) s[j][i] *= inv;
    }

    // ================= Pass 2: weighted v sum =================
    for (int c = 0; c < 3; c++) { stage(vb, c); cp_commit(); }

#pragma unroll 1
    for (int c = 0; c < C_; c++) {
        if (c + 3 < C_) stage(vb, c + 3);
        cp_commit();
        cp_wait3();
        __syncthreads();

        float acc[4] = {0.f, 0.f, 0.f, 0.f};
        const int bi = c & (NS - 1);
#pragma unroll
        for (int dy = 0; dy < 3; dy++) {
            const float* rp = &ring[bi][y + dy][4 + w0];
            const float4 m = *reinterpret_cast<const float4*>(rp);
            const float a[6] = {rp[-1], m.x, m.y, m.z, m.w, rp[4]};
#pragma unroll
            for (int j = 0; j < 4; j++)
#pragma unroll
                for (int dx = 0; dx < 3; dx++)
                    acc[j] = fmaf(s[j][dy * 3 + dx], a[j + dx], acc[j]);
        }

        float4 o;
        o.x = acc[0]; o.y = acc[1]; o.z = acc[2]; o.w = acc[3];
        *reinterpret_cast<float4*>(ob + (size_t)c * HW_ + rowoff) = o;
        __syncthreads();
    }
}

extern "C" void kernel_launch(void* const* d_in, const int* in_sizes, int n_in,
                              void* d_out, int out_size)
{
    const float* q = (const float*)d_in[0];
    const float* k = (const float*)d_in[1];
    const float* v = (const float*)d_in[2];
    float* out = (float*)d_out;

    dim3 block(256);
    dim3 grid(H_ / TH, B_);     // 64 x 8 = 512 blocks
    conv_attn_pipe<<<grid, block>>>(q, k, v, out);
}